// round 12
// baseline (speedup 1.0000x reference)
#include <cuda_runtime.h>
#include <cuda_fp16.h>
#include <cstdint>

#define DIM      4096
#define NPAIRS   2048
#define GRD      64
#define P_TILE   8                               // pairs per tile
#define THREADS  1024
#define SLOTS    4                               // pair-slots (2 pairs each)
#define BSTEP    (THREADS / SLOTS)               // 256 batch rows per iter
#define GSIZE    2                               // iterations per task
#define TPG      (GSIZE * BSTEP)                 // 512 rows per task
#define TPT      16                              // tasks per tile (8192/512)
#define GRID_ELEMS (GRD * GRD)                   // 4096 cells per pair
#define SMEM_BYTES (P_TILE * GRID_ELEMS * 4)     // 128 KB (half2 dup-pair cells)
#define XSTR     (BSTEP * (DIM / 4))             // float4 stride per iteration
#define OSTR     (BSTEP * (NPAIRS / 2))          // float2 stride per iteration

__global__ void __launch_bounds__(THREADS, 1)
pair_bilinear_kernel(const float* __restrict__ x,
                     const float* __restrict__ pairW,
                     const float* __restrict__ Y,
                     float* __restrict__ out,
                     int total_tasks)
{
    extern __shared__ __half2 sY[];  // [P_TILE][64][64] : cell = {Y[r][c], Y[r][c+1]}

    const int tid = threadIdx.x;
    const int sl  = tid & (SLOTS - 1);   // pair-slot 0..3 -> pairs 2sl, 2sl+1
    const int bs  = tid >> 2;            // batch sub-index 0..255

    // Balanced contiguous task range for this block (tile-major order)
    const long long tt = total_tasks;
    const int nb = gridDim.x;
    const int t0 = (int)((tt * blockIdx.x) / nb);
    const int t1 = (int)((tt * (blockIdx.x + 1)) / nb);

    const __half2* __restrict__ sA = sY + (2 * sl) * GRID_ELEMS;
    const __half2* __restrict__ sB = sA + GRID_ELEMS;

    // ── Prefetch x + weights for the first task (overlaps first staging) ──
    float4 xa[GSIZE];
    float4 wAc, wBc;
    {
        const int tile = t0 / TPT, grp = t0 % TPT;
        const int pA = tile * P_TILE + 2 * sl;
        const float4* __restrict__ xp = reinterpret_cast<const float4*>(x)
            + (size_t)(grp * TPG + bs) * (DIM / 4) + (pA >> 1);
        #pragma unroll
        for (int i = 0; i < GSIZE; i++) xa[i] = xp[i * XSTR];
        wAc = reinterpret_cast<const float4*>(pairW)[pA];
        wBc = reinterpret_cast<const float4*>(pairW)[pA + 1];
    }

    int cur_tile = -1;

    for (int t = t0; t < t1; ++t) {
        const int tile = t / TPT;
        const int grp  = t % TPT;

        // ── Stage tile grid on tile change (≤3 per block; L2-hot re-reads) ──
        if (tile != cur_tile) {
            if (cur_tile >= 0) __syncthreads();   // finish reads of old grid
            const float4* __restrict__ Yg = reinterpret_cast<const float4*>(Y)
                + (size_t)tile * P_TILE * (GRID_ELEMS / 4);
            uint4* __restrict__ sY4 = reinterpret_cast<uint4*>(sY);
            #pragma unroll
            for (int i = tid; i < P_TILE * GRID_ELEMS / 4; i += THREADS) {
                const float4 v = Yg[i];
                const int c4 = i & 15;
                const float vnext = (c4 < 15)
                    ? *reinterpret_cast<const float*>(Yg + i + 1)
                    : v.w;   // cell 63 never read
                __half2 h[4];
                h[0] = __floats2half2_rn(v.x, v.y);
                h[1] = __floats2half2_rn(v.y, v.z);
                h[2] = __floats2half2_rn(v.z, v.w);
                h[3] = __floats2half2_rn(v.w, vnext);
                sY4[i] = *reinterpret_cast<const uint4*>(h);   // STS.128
            }
            __syncthreads();
            cur_tile = tile;
        }

        // ── Prefetch next task's x + weights (independent of smem) ────────
        float4 xb[GSIZE];
        float4 wA2, wB2;
        if (t + 1 < t1) {
            const int tl2 = (t + 1) / TPT, g2 = (t + 1) % TPT;
            const int pA2 = tl2 * P_TILE + 2 * sl;
            const float4* __restrict__ xp2 = reinterpret_cast<const float4*>(x)
                + (size_t)(g2 * TPG + bs) * (DIM / 4) + (pA2 >> 1);
            #pragma unroll
            for (int i = 0; i < GSIZE; i++) xb[i] = xp2[i * XSTR];
            wA2 = reinterpret_cast<const float4*>(pairW)[pA2];   // L1-hit if same tile
            wB2 = reinterpret_cast<const float4*>(pairW)[pA2 + 1];
        }

        // ── Process current task: GSIZE iterations of 256 rows ────────────
        const int pA = tile * P_TILE + 2 * sl;
        float2* __restrict__ op = reinterpret_cast<float2*>(
            out + (size_t)(grp * TPG + bs) * NPAIRS + pA);

        __half2 tA[GSIZE], bA[GSIZE], tB[GSIZE], bB[GSIZE];
        float frA[GSIZE], fcA[GSIZE], frB[GSIZE], fcB[GSIZE];

        #pragma unroll
        for (int i = 0; i < GSIZE; i++) {
            const float a0 = fmaf(xa[i].x, wAc.x, xa[i].y * wAc.z);
            const float a1 = fmaf(xa[i].x, wAc.y, xa[i].y * wAc.w);
            const float b0 = fmaf(xa[i].z, wBc.x, xa[i].w * wBc.z);
            const float b1 = fmaf(xa[i].z, wBc.y, xa[i].w * wBc.w);

            const float gA0 = fminf(fmaxf(a0 * 63.0f, 0.0f), 63.0f);
            const float gA1 = fminf(fmaxf(a1 * 63.0f, 0.0f), 63.0f);
            const float gB0 = fminf(fmaxf(b0 * 63.0f, 0.0f), 63.0f);
            const float gB1 = fminf(fmaxf(b1 * 63.0f, 0.0f), 63.0f);

            const int rA = min((int)gA0, 62), cA = min((int)gA1, 62);
            const int rB = min((int)gB0, 62), cB = min((int)gB1, 62);
            frA[i] = gA0 - (float)rA;  fcA[i] = gA1 - (float)cA;
            frB[i] = gB0 - (float)rB;  fcB[i] = gB1 - (float)cB;

            const int baseA = (rA << 6) + cA;
            const int baseB = (rB << 6) + cB;
            tA[i] = sA[baseA];  bA[i] = sA[baseA + GRD];
            tB[i] = sB[baseB];  bB[i] = sB[baseB + GRD];
        }

        #pragma unroll
        for (int i = 0; i < GSIZE; i++) {
            const float2 ta = __half22float2(tA[i]);
            const float2 ba = __half22float2(bA[i]);
            const float2 tb = __half22float2(tB[i]);
            const float2 bb = __half22float2(bB[i]);

            const float topA = fmaf(fcA[i], ta.y - ta.x, ta.x);
            const float botA = fmaf(fcA[i], ba.y - ba.x, ba.x);
            const float topB = fmaf(fcB[i], tb.y - tb.x, tb.x);
            const float botB = fmaf(fcB[i], bb.y - bb.x, bb.x);

            float2 o;
            o.x = fmaf(frA[i], botA - topA, topA);
            o.y = fmaf(frB[i], botB - topB, topB);
            *op = o;                             // STG.64
            op += OSTR;
        }

        #pragma unroll
        for (int i = 0; i < GSIZE; i++) xa[i] = xb[i];
        wAc = wA2;  wBc = wB2;
    }
}

extern "C" void kernel_launch(void* const* d_in, const int* in_sizes, int n_in,
                              void* d_out, int out_size)
{
    const float* x     = (const float*)d_in[0];
    const float* pairW = (const float*)d_in[1];
    const float* Y     = (const float*)d_in[2];
    float* out         = (float*)d_out;

    const int batch = in_sizes[0] / DIM;                 // 8192
    const int total_tasks = (NPAIRS / P_TILE) * (batch / TPG);   // 256*16 = 4096

    int dev = 0, nsm = 148;
    cudaGetDevice(&dev);
    cudaDeviceGetAttribute(&nsm, cudaDevAttrMultiProcessorCount, dev);

    cudaFuncSetAttribute(pair_bilinear_kernel,
                         cudaFuncAttributeMaxDynamicSharedMemorySize, SMEM_BYTES);

    pair_bilinear_kernel<<<nsm, THREADS, SMEM_BYTES>>>(x, pairW, Y, out, total_tasks);
}

// round 13
// speedup vs baseline: 1.3664x; 1.3664x over previous
#include <cuda_runtime.h>
#include <cuda_fp16.h>
#include <cstdint>

#define DIM      4096
#define NPAIRS   2048
#define GRD      64
#define P_TILE   8                               // pairs per tile
#define THREADS  1024
#define SLOTS    4                               // pair-slots (2 pairs each)
#define BSTEP    (THREADS / SLOTS)               // 256 batch rows per iter
#define GSIZE    2                               // iterations per task
#define TPG      (GSIZE * BSTEP)                 // 512 rows per task
#define TPT      16                              // tasks per tile (8192/512)
#define GRID_ELEMS (GRD * GRD)                   // 4096 cells per pair
#define SMEM_BYTES (P_TILE * GRID_ELEMS * 4)     // 128 KB (half2 dup-pair cells)
#define XSTR     (BSTEP * (DIM / 4))             // float4 stride per iteration
#define OSTR     (BSTEP * (NPAIRS / 2))          // float2 stride per iteration

__device__ __forceinline__ void stage_tile(__half2* sY, const float* Y,
                                           int tile, int tid)
{
    const float4* __restrict__ Yg = reinterpret_cast<const float4*>(Y)
        + (size_t)tile * P_TILE * (GRID_ELEMS / 4);
    uint4* __restrict__ sY4 = reinterpret_cast<uint4*>(sY);
    #pragma unroll
    for (int i = tid; i < P_TILE * GRID_ELEMS / 4; i += THREADS) {
        const float4 v = Yg[i];
        const int c4 = i & 15;
        const float vnext = (c4 < 15) ? *reinterpret_cast<const float*>(Yg + i + 1)
                                      : v.w;   // cell 63 never read
        __half2 h[4];
        h[0] = __floats2half2_rn(v.x, v.y);
        h[1] = __floats2half2_rn(v.y, v.z);
        h[2] = __floats2half2_rn(v.z, v.w);
        h[3] = __floats2half2_rn(v.w, vnext);
        sY4[i] = *reinterpret_cast<const uint4*>(h);   // STS.128, conflict-free
    }
}

__global__ void __launch_bounds__(THREADS, 1)
pair_bilinear_kernel(const float* __restrict__ x,
                     const float* __restrict__ pairW,
                     const float* __restrict__ Y,
                     float* __restrict__ out,
                     int total_tasks)
{
    extern __shared__ __half2 sY[];

    const int tid = threadIdx.x;
    const int sl  = tid & (SLOTS - 1);   // pair-slot 0..3 -> pairs 2sl, 2sl+1
    const int bs  = tid >> 2;            // batch sub-index 0..255

    // Balanced contiguous task range (tile-major order)
    const int nb = gridDim.x;
    const int t0 = (int)(((long long)total_tasks * blockIdx.x) / nb);
    const int t1 = (int)(((long long)total_tasks * (blockIdx.x + 1)) / nb);

    const __half2* __restrict__ sA = sY + (2 * sl) * GRID_ELEMS;
    const __half2* __restrict__ sB = sA + GRID_ELEMS;

    int tile = t0 / TPT;
    int grp  = t0 % TPT;

    // ── Prefetch first task's x (overlaps first staging) ─────────────────
    float4 xa[GSIZE];
    {
        const int pA = tile * P_TILE + 2 * sl;
        const float4* __restrict__ xp = reinterpret_cast<const float4*>(x)
            + (size_t)(grp * TPG + bs) * (DIM / 4) + (pA >> 1);
        #pragma unroll
        for (int i = 0; i < GSIZE; i++) xa[i] = xp[i * XSTR];
    }

    stage_tile(sY, Y, tile, tid);
    __syncthreads();

    float4 wAc = reinterpret_cast<const float4*>(pairW)[tile * P_TILE + 2 * sl];
    float4 wBc = reinterpret_cast<const float4*>(pairW)[tile * P_TILE + 2 * sl + 1];

    for (int t = t0; t < t1; ++t) {
        // next task coordinates (incremental, no divides)
        int g2 = grp + 1, tl2 = tile;
        if (g2 == TPT) { g2 = 0; tl2 = tile + 1; }

        // ── Prefetch next task's x (independent of smem state) ────────────
        float4 xb[GSIZE];
        if (t + 1 < t1) {
            const int pA2 = tl2 * P_TILE + 2 * sl;
            const float4* __restrict__ xp2 = reinterpret_cast<const float4*>(x)
                + (size_t)(g2 * TPG + bs) * (DIM / 4) + (pA2 >> 1);
            #pragma unroll
            for (int i = 0; i < GSIZE; i++) xb[i] = xp2[i * XSTR];
        }

        // ── Process current task ───────────────────────────────────────────
        const int pA = tile * P_TILE + 2 * sl;
        float2* __restrict__ op = reinterpret_cast<float2*>(
            out + (size_t)(grp * TPG + bs) * NPAIRS + pA);

        __half2 tA[GSIZE], bA[GSIZE], tB[GSIZE], bB[GSIZE];
        float frA[GSIZE], fcA[GSIZE], frB[GSIZE], fcB[GSIZE];

        #pragma unroll
        for (int i = 0; i < GSIZE; i++) {
            const float a0 = fmaf(xa[i].x, wAc.x, xa[i].y * wAc.z);
            const float a1 = fmaf(xa[i].x, wAc.y, xa[i].y * wAc.w);
            const float b0 = fmaf(xa[i].z, wBc.x, xa[i].w * wBc.z);
            const float b1 = fmaf(xa[i].z, wBc.y, xa[i].w * wBc.w);

            const float gA0 = fminf(fmaxf(a0 * 63.0f, 0.0f), 63.0f);
            const float gA1 = fminf(fmaxf(a1 * 63.0f, 0.0f), 63.0f);
            const float gB0 = fminf(fmaxf(b0 * 63.0f, 0.0f), 63.0f);
            const float gB1 = fminf(fmaxf(b1 * 63.0f, 0.0f), 63.0f);

            const int rA = min((int)gA0, 62), cA = min((int)gA1, 62);
            const int rB = min((int)gB0, 62), cB = min((int)gB1, 62);
            frA[i] = gA0 - (float)rA;  fcA[i] = gA1 - (float)cA;
            frB[i] = gB0 - (float)rB;  fcB[i] = gB1 - (float)cB;

            const int baseA = (rA << 6) + cA;
            const int baseB = (rB << 6) + cB;
            tA[i] = sA[baseA];  bA[i] = sA[baseA + GRD];
            tB[i] = sB[baseB];  bB[i] = sB[baseB + GRD];
        }

        #pragma unroll
        for (int i = 0; i < GSIZE; i++) {
            const float2 ta = __half22float2(tA[i]);
            const float2 ba = __half22float2(bA[i]);
            const float2 tb = __half22float2(tB[i]);
            const float2 bb = __half22float2(bB[i]);

            const float topA = fmaf(fcA[i], ta.y - ta.x, ta.x);
            const float botA = fmaf(fcA[i], ba.y - ba.x, ba.x);
            const float topB = fmaf(fcB[i], tb.y - tb.x, tb.x);
            const float botB = fmaf(fcB[i], bb.y - bb.x, bb.x);

            float2 o;
            o.x = fmaf(frA[i], botA - topA, topA);
            o.y = fmaf(frB[i], botB - topB, topB);
            *op = o;                             // STG.64
            op += OSTR;
        }

        #pragma unroll
        for (int i = 0; i < GSIZE; i++) xa[i] = xb[i];

        // ── Tile boundary: restage (≤1 per block typically; L2-hot) ───────
        if (tl2 != tile && t + 1 < t1) {
            __syncthreads();                     // drain reads of old grid
            stage_tile(sY, Y, tl2, tid);
            __syncthreads();
            wAc = reinterpret_cast<const float4*>(pairW)[tl2 * P_TILE + 2 * sl];
            wBc = reinterpret_cast<const float4*>(pairW)[tl2 * P_TILE + 2 * sl + 1];
        }
        tile = tl2;
        grp  = g2;
    }
}

extern "C" void kernel_launch(void* const* d_in, const int* in_sizes, int n_in,
                              void* d_out, int out_size)
{
    const float* x     = (const float*)d_in[0];
    const float* pairW = (const float*)d_in[1];
    const float* Y     = (const float*)d_in[2];
    float* out         = (float*)d_out;

    const int batch = in_sizes[0] / DIM;                       // 8192
    const int total_tasks = (NPAIRS / P_TILE) * (batch / TPG); // 4096

    int dev = 0, nsm = 148;
    cudaGetDevice(&dev);
    cudaDeviceGetAttribute(&nsm, cudaDevAttrMultiProcessorCount, dev);

    cudaFuncSetAttribute(pair_bilinear_kernel,
                         cudaFuncAttributeMaxDynamicSharedMemorySize, SMEM_BYTES);

    pair_bilinear_kernel<<<2 * nsm, THREADS, SMEM_BYTES>>>(x, pairW, Y, out,
                                                           total_tasks);
}

// round 14
// speedup vs baseline: 1.4866x; 1.0880x over previous
#include <cuda_runtime.h>
#include <cuda_fp16.h>
#include <cstdint>

#define DIM      4096
#define NPAIRS   2048
#define GRD      64
#define P_TILE   8                               // pairs staged per block
#define THREADS  1024
#define SLOTS    4                               // pair-slots (2 pairs each)
#define BSTEP    (THREADS / SLOTS)               // 256 batch rows per iter
#define GRID_ELEMS (GRD * GRD)                   // 4096 cells per pair
#define SMEM_BYTES (P_TILE * GRID_ELEMS * 4)     // 128 KB (half2 dup-pair cells)
#define GSIZE    2                               // iterations per pipeline group

__global__ void __launch_bounds__(THREADS, 1)
pair_bilinear_kernel(const float* __restrict__ x,
                     const float* __restrict__ pairW,
                     const float* __restrict__ Y,
                     float* __restrict__ out,
                     int groups)
{
    extern __shared__ __half2 sY[];  // [P_TILE][64][64] : cell = {Y[r][c], Y[r][c+1]}

    const int p0 = blockIdx.x * P_TILE;
    const int tid = threadIdx.x;

    const int sl = tid & (SLOTS - 1);    // pair-slot (0..3) -> pairs 2sl,2sl+1
    const int bs = tid >> 2;             // batch sub-index (0..255)
    const int pA = p0 + 2 * sl;          // first pair of this thread

    // x: 4 consecutive floats per (b, slot) -> one float4
    const float4* __restrict__ xp =
        reinterpret_cast<const float4*>(x) + (size_t)bs * (DIM / 4) + (pA >> 1);
    const int XSTR = BSTEP * (DIM / 4);

    // ── Hoisted first x-group prefetch: overlaps Y staging below ─────────
    float4 xa[GSIZE];
    #pragma unroll
    for (int i = 0; i < GSIZE; i++) xa[i] = xp[i * XSTR];
    xp += GSIZE * XSTR;

    // ── Stage: duplicated-pair fp16 grid from fp32 Y (once per block) ────
    // vnext (neighbor of v.w) comes from lane+1 via shfl: with i = tid + k*1024,
    // the lanes whose quad ends a 64-float row (c4 == 15, i.e. tid%16 == 15,
    // lanes 15 and 31) never need vnext — and lane 31 is exactly such a lane,
    // so the shfl wrap value is never consumed.
    {
        const float4* __restrict__ Yg =
            reinterpret_cast<const float4*>(Y) + p0 * (GRID_ELEMS / 4);
        uint4* __restrict__ sY4 = reinterpret_cast<uint4*>(sY);
        #pragma unroll
        for (int i = tid; i < P_TILE * GRID_ELEMS / 4; i += THREADS) {
            const float4 v = __ldcs(Yg + i);                 // stream Y, evict-first
            const float vnext = __shfl_down_sync(0xFFFFFFFFu, v.x, 1);
            __half2 h[4];
            h[0] = __floats2half2_rn(v.x, v.y);
            h[1] = __floats2half2_rn(v.y, v.z);
            h[2] = __floats2half2_rn(v.z, v.w);
            h[3] = __floats2half2_rn(v.w, vnext);            // garbage only when c4==15 (unread)
            sY4[i] = *reinterpret_cast<const uint4*>(h);     // STS.128, conflict-free
        }
    }
    __syncthreads();

    const float4 wA = *(reinterpret_cast<const float4*>(pairW) + pA);
    const float4 wB = *(reinterpret_cast<const float4*>(pairW) + pA + 1);

    const __half2* __restrict__ sA = sY + (2 * sl) * GRID_ELEMS;
    const __half2* __restrict__ sB = sA + GRID_ELEMS;

    float2* __restrict__ op =
        reinterpret_cast<float2*>(out + (size_t)bs * NPAIRS + pA);
    const int OSTR = BSTEP * (NPAIRS / 2);

    // ── Software-pipelined main loop (16 groups, whole batch) ────────────
    for (int gset = 0; gset < groups; ++gset) {
        float4 xb[GSIZE];
        if (gset + 1 < groups) {
            #pragma unroll
            for (int i = 0; i < GSIZE; i++) xb[i] = xp[i * XSTR];
            xp += GSIZE * XSTR;
        }

        __half2 tA[GSIZE], bA[GSIZE], tB[GSIZE], bB[GSIZE];
        float frA[GSIZE], fcA[GSIZE], frB[GSIZE], fcB[GSIZE];

        // Phase A: addresses + all 4*GSIZE gathers in flight
        #pragma unroll
        for (int i = 0; i < GSIZE; i++) {
            const float a0 = fmaf(xa[i].x, wA.x, xa[i].y * wA.z);
            const float a1 = fmaf(xa[i].x, wA.y, xa[i].y * wA.w);
            const float b0 = fmaf(xa[i].z, wB.x, xa[i].w * wB.z);
            const float b1 = fmaf(xa[i].z, wB.y, xa[i].w * wB.w);

            const float gA0 = fminf(fmaxf(a0 * 63.0f, 0.0f), 63.0f);
            const float gA1 = fminf(fmaxf(a1 * 63.0f, 0.0f), 63.0f);
            const float gB0 = fminf(fmaxf(b0 * 63.0f, 0.0f), 63.0f);
            const float gB1 = fminf(fmaxf(b1 * 63.0f, 0.0f), 63.0f);

            const int rA = min((int)gA0, 62), cA = min((int)gA1, 62);
            const int rB = min((int)gB0, 62), cB = min((int)gB1, 62);
            frA[i] = gA0 - (float)rA;  fcA[i] = gA1 - (float)cA;
            frB[i] = gB0 - (float)rB;  fcB[i] = gB1 - (float)cB;

            const int baseA = (rA << 6) + cA;
            const int baseB = (rB << 6) + cB;
            tA[i] = sA[baseA];  bA[i] = sA[baseA + GRD];
            tB[i] = sB[baseB];  bB[i] = sB[baseB + GRD];
        }

        // Phase B: blend + vectorized streaming store
        #pragma unroll
        for (int i = 0; i < GSIZE; i++) {
            const float2 ta = __half22float2(tA[i]);
            const float2 ba = __half22float2(bA[i]);
            const float2 tb = __half22float2(tB[i]);
            const float2 bb = __half22float2(bB[i]);

            const float topA = fmaf(fcA[i], ta.y - ta.x, ta.x);
            const float botA = fmaf(fcA[i], ba.y - ba.x, ba.x);
            const float topB = fmaf(fcB[i], tb.y - tb.x, tb.x);
            const float botB = fmaf(fcB[i], bb.y - bb.x, bb.x);

            float2 o;
            o.x = fmaf(frA[i], botA - topA, topA);
            o.y = fmaf(frB[i], botB - topB, topB);
            __stcs(op, o);                       // STG.64, evict-first
            op += OSTR;
        }

        #pragma unroll
        for (int i = 0; i < GSIZE; i++) xa[i] = xb[i];
    }
}

extern "C" void kernel_launch(void* const* d_in, const int* in_sizes, int n_in,
                              void* d_out, int out_size)
{
    const float* x     = (const float*)d_in[0];
    const float* pairW = (const float*)d_in[1];
    const float* Y     = (const float*)d_in[2];
    float* out         = (float*)d_out;

    const int batch = in_sizes[0] / DIM;               // 8192
    const int groups = batch / (GSIZE * BSTEP);        // 8192 / 512 = 16

    cudaFuncSetAttribute(pair_bilinear_kernel,
                         cudaFuncAttributeMaxDynamicSharedMemorySize, SMEM_BYTES);

    dim3 grid(NPAIRS / P_TILE, 1);   // 256 persistent pair-tile blocks (lockstep)
    pair_bilinear_kernel<<<grid, THREADS, SMEM_BYTES>>>(x, pairW, Y, out, groups);
}